// round 12
// baseline (speedup 1.0000x reference)
#include <cuda_runtime.h>
#include <cuda_fp16.h>
#include <cstdint>
#include <cstddef>

// ---------------------------------------------------------------------------
// Out[b] = [W_e | W_h](128x256) @ [e_vw[b]; h_w[b]](256x512) + (b_e + b_h)
// B=1024, M=128, K=256, N=512.
// Persistent CTA (NB=4 batches), whole prepacked-fp16 W resident in smem.
// B: cp.async fp32 5-stage ring, 4 chunks in flight.
// Split-K warp grid 2m x 2n x 2k (warp tile 64x32, one 16-k half each).
// R11 fix: __syncthreads() between compute and the scratch-store phase of
// the per-batch ks-reduction (kh=1 warps were overwriting the B stage while
// kh=0 warps still read it -> rel_err 5.6e-3).
// ---------------------------------------------------------------------------

#define A_PITCH_H     264                     // halves per W row (528 B)
#define A_TOTAL_BYTES (128 * A_PITCH_H * 2)   // 67584
#define B_PITCH_F     68                      // floats per B row
#define B_STAGE_F     (32 * B_PITCH_F)        // 2176 floats
#define B_STAGE_BYTES (B_STAGE_F * 4)         // 8704
#define B_STAGES      5
#define SMEM_TOTAL    (A_TOTAL_BYTES + B_STAGES * B_STAGE_BYTES)  // 111104
#define NB            4
#define NCHUNK        (NB * 8)                // 32 K-chunks

__device__ __half g_W[128 * 256];     // [m][k] fp16, k-contiguous
__device__ float  g_bias[128];

__global__ __launch_bounds__(256)
void prep_kernel(const float* __restrict__ W_e, const float* __restrict__ W_h,
                 const float* __restrict__ b_e, const float* __restrict__ b_h) {
    const int idx = blockIdx.x * 256 + threadIdx.x;     // 0..32767
    const int m = idx >> 8, k = idx & 255;
    const float v = (k < 128) ? W_e[m * 128 + k] : W_h[m * 128 + (k - 128)];
    g_W[idx] = __float2half(v);
    if (idx < 128) g_bias[idx] = b_e[idx] + b_h[idx];
}

static __device__ __forceinline__ uint32_t smem_u32(const void* p) {
    uint32_t a;
    asm("{ .reg .u64 t; cvta.to.shared.u64 t, %1; cvt.u32.u64 %0, t; }"
        : "=r"(a) : "l"(p));
    return a;
}
static __device__ __forceinline__ void ldmx4(uint32_t* r, uint32_t addr) {
    asm volatile("ldmatrix.sync.aligned.m8n8.x4.shared.b16 {%0,%1,%2,%3}, [%4];"
                 : "=r"(r[0]), "=r"(r[1]), "=r"(r[2]), "=r"(r[3]) : "r"(addr));
}
static __device__ __forceinline__ void mma16816(float* d, const uint32_t* a,
                                                uint32_t b0, uint32_t b1) {
    asm volatile(
        "mma.sync.aligned.m16n8k16.row.col.f32.f16.f16.f32 "
        "{%0,%1,%2,%3}, {%4,%5,%6,%7}, {%8,%9}, {%0,%1,%2,%3};"
        : "+f"(d[0]), "+f"(d[1]), "+f"(d[2]), "+f"(d[3])
        : "r"(a[0]), "r"(a[1]), "r"(a[2]), "r"(a[3]), "r"(b0), "r"(b1));
}
static __device__ __forceinline__ uint32_t packh2(float x, float y) {
    __half2 h = __floats2half2_rn(x, y);
    return *reinterpret_cast<uint32_t*>(&h);
}
static __device__ __forceinline__ void cp16(uint32_t smem_addr, const void* g) {
    asm volatile("cp.async.cg.shared.global [%0], [%1], 16;"
                 :: "r"(smem_addr), "l"(g) : "memory");
}
static __device__ __forceinline__ void cp_commit() {
    asm volatile("cp.async.commit_group;" ::: "memory");
}
template <int N>
static __device__ __forceinline__ void cp_wait() {
    asm volatile("cp.async.wait_group %0;" :: "n"(N) : "memory");
}

__global__ __launch_bounds__(256, 2)
void msg_kernel(const float* __restrict__ h_w, const float* __restrict__ e_vw,
                float* __restrict__ out) {
    extern __shared__ char smem[];
    __shared__ float sbias[128];

    const int tid  = threadIdx.x;
    const int lane = tid & 31;
    const int wid  = tid >> 5;
    const int b0   = blockIdx.y * NB;          // first batch of this CTA
    const int n0   = blockIdx.x << 6;          // 0..448 step 64

    if (tid < 128) sbias[tid] = g_bias[tid];

    const uint32_t sA = smem_u32(smem);
    const uint32_t sB = sA + A_TOTAL_BYTES;
    float* Bbase = reinterpret_cast<float*>(smem + A_TOTAL_BYTES);

    // -------- A prologue: whole prepacked W -> smem (one group) --------
    #pragma unroll
    for (int t = 0; t < 16; t++) {
        const int idx = tid + (t << 8);        // 4096 x 16B
        const int m = idx >> 5, q = idx & 31;
        cp16(sA + (uint32_t)(m * 528 + q * 16), g_W + m * 256 + q * 8);
    }
    cp_commit();                               // group: A

    auto cp_B = [&](int ci) {                  // global chunk ci -> stage ci%5
        const int bat = b0 + (ci >> 3);
        const int k0  = (ci & 7) << 5;
        const float* X = (k0 < 128)
            ? (e_vw + (size_t)bat * 65536 + n0 + (size_t)k0 * 512)
            : (h_w  + (size_t)bat * 65536 + n0 + (size_t)(k0 - 128) * 512);
        const uint32_t bst = sB + (uint32_t)(ci % B_STAGES) * B_STAGE_BYTES;
        #pragma unroll
        for (int t = 0; t < 2; t++) {
            const int idx = tid + (t << 8);
            const int k = idx >> 4, n4 = (idx & 15) << 2;   // 32 rows x 64 n
            cp16(bst + (uint32_t)(k * B_PITCH_F + n4) * 4,
                 X + (size_t)k * 512 + n4);
        }
        cp_commit();
    };

    cp_B(0); cp_B(1); cp_B(2); cp_B(3);        // 4 chunks in flight

    // Split-K warp grid: wm in {0,64}, wn in {0,32}, kh in {0,1}
    const int wm = (wid & 1) << 6;
    const int wn = ((wid >> 1) & 1) << 5;
    const int kh = wid >> 2;                   // 16-k half of each 32-k chunk

    float acc[4][4][4];                        // 64m x 32n warp tile
    #pragma unroll
    for (int i = 0; i < 4; i++)
        #pragma unroll
        for (int t = 0; t < 4; t++)
            #pragma unroll
            for (int r = 0; r < 4; r++) acc[i][t][r] = 0.f;

    const int j8  = lane & 7;
    const int sel = lane >> 3;
    const int r0  = lane >> 2;
    const int c0  = (lane & 3) << 1;

    // A ldmatrix base per i (row + lane-col + kh offset baked in)
    uint32_t aRow[4];
    #pragma unroll
    for (int i = 0; i < 4; i++)
        aRow[i] = sA + (uint32_t)((wm + (i << 4) + ((sel & 1) << 3) + j8) * 528
                                  + (((sel >> 1) << 3) + (kh << 4)) * 2);
    // B frag base offset (floats): row = kh*16 + 2*(lane&3), col = wn + lane>>2
    const int bOff = ((kh << 4) + ((lane & 3) << 1)) * B_PITCH_F + wn + (lane >> 2);

    // -------- mainloop: 32 chunks, one barrier per chunk --------
    for (int ci = 0; ci < NCHUNK; ci++) {
        if      (ci < NCHUNK - 3)  cp_wait<3>();
        else if (ci == NCHUNK - 3) cp_wait<2>();
        else if (ci == NCHUNK - 2) cp_wait<1>();
        else                       cp_wait<0>();
        __syncthreads();          // chunk-ci visible; stage (ci-1)%5 free
        if (ci + 4 < NCHUNK) cp_B(ci + 4);

        const uint32_t kBytes = (uint32_t)((ci & 7) << 6);   // 32 halves
        const float* Bs = Bbase + (ci % B_STAGES) * B_STAGE_F;

        uint32_t afr[4][4];
        #pragma unroll
        for (int i = 0; i < 4; i++)
            ldmx4(afr[i], aRow[i] + kBytes);

        uint32_t bq[4][2];
        #pragma unroll
        for (int t = 0; t < 4; t++) {
            const float* p = Bs + bOff + (t << 3);
            const float f0 = p[0];
            const float f1 = p[B_PITCH_F];
            const float f2 = p[8 * B_PITCH_F];
            const float f3 = p[9 * B_PITCH_F];
            bq[t][0] = packh2(f0, f1);
            bq[t][1] = packh2(f2, f3);
        }
        #pragma unroll
        for (int i = 0; i < 4; i++)
            #pragma unroll
            for (int t = 0; t < 4; t++)
                mma16816(acc[i][t], afr[i], bq[t][0], bq[t][1]);

        // -------- per-batch: ks-reduction + epilogue --------
        if ((ci & 7) == 7) {
            const int bat = b0 + (ci >> 3);
            float* outp = out + (size_t)bat * 65536 + n0;
            // R11 FIX: all warps must finish READING this B stage (compute
            // above) before kh=1 warps overwrite it with partials.
            __syncthreads();
            // scratch = stage just consumed (ci%5); next cp.async writer of
            // this stage is cp_B(ci+5), issued after the next loop-top
            // barrier -> no writer overlaps the reduction below.
            float* my = Bbase + (ci % B_STAGES) * B_STAGE_F + (wid & 3) * 544;
            #pragma unroll
            for (int r = 0; r < 4; r++) {
                if (kh == 1) {                 // producers: store partials
                    #pragma unroll
                    for (int t = 0; t < 4; t++) {
                        const int c = c0 + (t << 3);
                        *reinterpret_cast<float2*>(my + r0 * 34 + c) =
                            make_float2(acc[r][t][0], acc[r][t][1]);
                        *reinterpret_cast<float2*>(my + (r0 + 8) * 34 + c) =
                            make_float2(acc[r][t][2], acc[r][t][3]);
                    }
                }
                __syncthreads();
                if (kh == 0) {                 // consumers: add + bias + STG
                    const int m = wm + (r << 4) + r0;
                    const float bias0 = sbias[m];
                    const float bias1 = sbias[m + 8];
                    #pragma unroll
                    for (int t = 0; t < 4; t++) {
                        const int c = c0 + (t << 3);
                        float2 p0 = *reinterpret_cast<float2*>(my + r0 * 34 + c);
                        float2 p1 = *reinterpret_cast<float2*>(my + (r0 + 8) * 34 + c);
                        float2 v0 = make_float2(acc[r][t][0] + p0.x + bias0,
                                                acc[r][t][1] + p0.y + bias0);
                        float2 v1 = make_float2(acc[r][t][2] + p1.x + bias1,
                                                acc[r][t][3] + p1.y + bias1);
                        *reinterpret_cast<float2*>(
                            outp + (size_t)m * 512 + wn + c) = v0;
                        *reinterpret_cast<float2*>(
                            outp + (size_t)(m + 8) * 512 + wn + c) = v1;
                    }
                }
                __syncthreads();               // LDS(r) done before STS(r+1)
            }
            #pragma unroll
            for (int i = 0; i < 4; i++)
                #pragma unroll
                for (int t = 0; t < 4; t++) {
                    acc[i][t][0] = 0.f; acc[i][t][1] = 0.f;
                    acc[i][t][2] = 0.f; acc[i][t][3] = 0.f;
                }
        }
    }
}

extern "C" void kernel_launch(void* const* d_in, const int* in_sizes, int n_in,
                              void* d_out, int out_size) {
    // metadata order: h_v(unused), h_w, e_vw, W_e, b_e, W_h, b_h
    const float* h_w  = (const float*)d_in[1];
    const float* e_vw = (const float*)d_in[2];
    const float* W_e  = (const float*)d_in[3];
    const float* b_e  = (const float*)d_in[4];
    const float* W_h  = (const float*)d_in[5];
    const float* b_h  = (const float*)d_in[6];
    float* out = (float*)d_out;

    prep_kernel<<<128, 256>>>(W_e, W_h, b_e, b_h);

    cudaFuncSetAttribute(msg_kernel, cudaFuncAttributeMaxDynamicSharedMemorySize,
                         SMEM_TOTAL);
    dim3 grid(8, 256);
    msg_kernel<<<grid, 256, SMEM_TOTAL>>>(h_w, e_vw, out);
}